// round 4
// baseline (speedup 1.0000x reference)
#include <cuda_runtime.h>
#include <cstdint>

// B=4, M_IN=16, M_OUT=32, C=32.  x:(4,16,32,32,32,32) fp32 -> out:(4,32,4,32) fp32
//
//   s1[b,m,c2] = sum_{c3,c4,c5} x          (s2 == s1)
//   s3[b,m,c3] = sum_{c2,c4,c5} x
//   s4[b,m,c4] = sum_{c2,c3,c5} x
//   W = alpha+beta+gamma+delta (16x32)
//   out[b,n,i,c] = sum_m S_i[b,m,c] * W[m,n],  S = [s1,s1,s3,s4]
//
// Kernel 1 (4096 blocks): one HALF-slice (b,m,c2,half) of 16384 floats.
//   Register f32x2 accumulators, evict-first streaming loads.
//   Epilogue writes partials TRANSPOSED so the tail reads contiguously.
// Kernel 2 (64 blocks): block = (b,i,c-octet). Stage A: contiguous float4
//   loads of L2-hot partials (2 threads/value). Stage B: tiny einsum.

__device__ float g_s1h [4096];           // [bid], bid = slice*2+half, slice=(b*16+m)*32+c2
__device__ float g_s3T [32 * 2048];      // [c3][slice]   (full sum over c4,c5; owner half writes)
__device__ float g_s4hT[32 * 4096];      // [c4][bid]     (partial over this half's c3)

__device__ __forceinline__ unsigned long long addx2(unsigned long long a,
                                                    unsigned long long b) {
    unsigned long long r;
    asm("add.rn.f32x2 %0, %1, %2;" : "=l"(r) : "l"(a), "l"(b));
    return r;
}
__device__ __forceinline__ float x2sum(unsigned long long a) {
    unsigned lo, hi;
    asm("mov.b64 {%0,%1}, %2;" : "=r"(lo), "=r"(hi) : "l"(a));
    return __uint_as_float(lo) + __uint_as_float(hi);
}
// evict-first 16B streaming load (read-once data; keep L2 for partials)
__device__ __forceinline__ ulonglong2 ldcs2(const ulonglong2* p) {
    ulonglong2 r;
    asm("ld.global.cs.v2.u64 {%0, %1}, [%2];" : "=l"(r.x), "=l"(r.y) : "l"(p));
    return r;
}

// ---------------- Kernel 1: half-slice reduction, register accumulators ----------------
__global__ void __launch_bounds__(256, 4)
k_reduce(const float* __restrict__ x) {
    const int t    = threadIdx.x;
    const int lane = t & 31;
    const int w    = t >> 5;
    const int bid  = blockIdx.x;          // half-slice id
    const int slice = bid >> 1;
    const int half  = bid & 1;

    const ulonglong2* __restrict__ xv =
        reinterpret_cast<const ulonglong2*>(x) + (size_t)bid * 4096; // 16384 floats

    __shared__ float s4buf[256];          // [warp][c4]
    __shared__ float wt[8];

    unsigned long long col[8];
#pragma unroll
    for (int s = 0; s < 8; ++s) col[s] = 0ull;

    float rows_tot = 0.f;                 // valid on lane 0
#pragma unroll
    for (int j = 0; j < 2; ++j) {
        const int k = w + j * 8;          // local row 0..15  (c3 = half*16 + k)
        const ulonglong2* __restrict__ p = xv + k * 256 + lane;

        ulonglong2 d[8];
#pragma unroll
        for (int s = 0; s < 8; ++s) d[s] = ldcs2(p + s * 32);   // 8 back-to-back LDG.128

        unsigned long long row = 0ull;
#pragma unroll
        for (int s = 0; s < 8; ++s) {
            unsigned long long v = addx2(d[s].x, d[s].y);  // {f0+f2, f1+f3}
            row    = addx2(row, v);
            col[s] = addx2(col[s], v);
        }
        float r = x2sum(row);
#pragma unroll
        for (int o = 16; o; o >>= 1) r += __shfl_down_sync(0xffffffffu, r, o);
        if (lane == 0) {
            g_s3T[(half * 16 + k) * 2048 + slice] = r;   // transposed: [c3][slice]
            rows_tot += r;
        }
    }

    // fold column accs: lanes in an octet share c4 = s*4 + (lane>>3)
#pragma unroll
    for (int s = 0; s < 8; ++s) {
        float cs = x2sum(col[s]);
        cs += __shfl_down_sync(0xffffffffu, cs, 4);
        cs += __shfl_down_sync(0xffffffffu, cs, 2);
        cs += __shfl_down_sync(0xffffffffu, cs, 1);
        if ((lane & 7) == 0) s4buf[w * 32 + s * 4 + (lane >> 3)] = cs;
    }
    if (lane == 0) wt[w] = rows_tot;
    __syncthreads();

    if (t < 32) {        // warp 0: cross-warp s4 fold + slice total
        float v = 0.f;
#pragma unroll
        for (int ww = 0; ww < 8; ++ww) v += s4buf[ww * 32 + t];
        g_s4hT[t * 4096 + bid] = v;                      // transposed: [c4][bid]
        if (t == 0) {
            float s = 0.f;
#pragma unroll
            for (int ww = 0; ww < 8; ++ww) s += wt[ww];
            g_s1h[bid] = s;
        }
    }
}

// ---------------- Kernel 2: single tail kernel, 64 blocks, contiguous loads ----------------
// block bid: b = bid>>4, i = (bid>>2)&3, oct = bid&3 (c in [oct*8, oct*8+8))
__global__ void __launch_bounds__(256)
k_tail(const float* __restrict__ a, const float* __restrict__ bb,
       const float* __restrict__ g, const float* __restrict__ d,
       float* __restrict__ out) {
    __shared__ float sW[512];             // [m][n]
    __shared__ float pp[256];             // per-thread partials
    __shared__ float sS[128];             // [m][cl]

    const int t   = threadIdx.x;
    const int bid = blockIdx.x;
    const int b   = bid >> 4;
    const int i   = (bid >> 2) & 3;
    const int oct = bid & 3;

    sW[t]       = a[t]       + bb[t]       + g[t]       + d[t];
    sW[t + 256] = a[t + 256] + bb[t + 256] + g[t + 256] + d[t + 256];

    // ---- stage A: build S[m][cl] (2 threads per value, contiguous float4 loads) ----
    const int pair = t >> 1;              // 0..127
    const int part = t & 1;
    const int m    = pair >> 3;           // 0..15
    const int cl   = pair & 7;
    const int c    = oct * 8 + cl;
    const int bm   = b * 16 + m;

    float v = 0.f;
    if (i < 2) {
        v = g_s1h[(bm * 32 + c) * 2 + part];           // c plays c2; part = half
    } else if (i == 2) {
        // sum over c2: g_s3T[c][bm*32 + 0..31], split 16/16 -> 4 float4 each
        const float4* __restrict__ p =
            reinterpret_cast<const float4*>(g_s3T + c * 2048 + bm * 32 + part * 16);
#pragma unroll
        for (int q = 0; q < 4; ++q) {
            float4 f = p[q];
            v += (f.x + f.y) + (f.z + f.w);
        }
    } else {
        // sum over (c2,half): g_s4hT[c][bm*64 + 0..63], split 32/32 -> 8 float4 each
        const float4* __restrict__ p =
            reinterpret_cast<const float4*>(g_s4hT + c * 4096 + bm * 64 + part * 32);
#pragma unroll
        for (int q = 0; q < 8; ++q) {
            float4 f = p[q];
            v += (f.x + f.y) + (f.z + f.w);
        }
    }
    pp[t] = v;
    __syncthreads();
    if (t < 128) sS[t] = pp[2 * t] + pp[2 * t + 1];
    __syncthreads();

    // ---- stage B: out[b,n,i,c] = sum_m S[m][cl] * W[m,n] ----
    const int n  = t >> 3;                // 0..31
    const int c2 = t & 7;                 // cl
    float acc = 0.f;
#pragma unroll
    for (int mm = 0; mm < 16; ++mm)
        acc += sS[mm * 8 + c2] * sW[mm * 32 + n];
    out[((b * 32 + n) * 4 + i) * 32 + oct * 8 + c2] = acc;
}

// ---------------- launch ----------------
extern "C" void kernel_launch(void* const* d_in, const int* in_sizes, int n_in,
                              void* d_out, int out_size) {
    const float* x     = (const float*)d_in[0];
    const float* alpha = (const float*)d_in[1];
    const float* beta  = (const float*)d_in[2];
    const float* gamma = (const float*)d_in[3];
    const float* delta = (const float*)d_in[4];

    k_reduce<<<4096, 256>>>(x);
    k_tail  <<<64, 256>>>(alpha, beta, gamma, delta, (float*)d_out);
}